// round 5
// baseline (speedup 1.0000x reference)
#include <cuda_runtime.h>

// IdentityResBlock, FFMA2 (fma.rn.f32x2) edition, alignment-fixed.
// hs row stride = 68 floats (272B, 16B-aligned for float4 stores).
// All shared tiles __align__(16) so LDS.128 / ld.shared.v2.u64 bases are legal.

#define N_NODES 200000
#define NTILES  3125          // 200000 / 64, exact
#define EPS_BN  1e-3f

typedef unsigned long long ull;

// ---- scratch (device globals; allocation-free per harness rules) ----
__device__ __align__(16) float g_y1[N_NODES * 64];
__device__ __align__(16) float g_h1[N_NODES * 64];
__device__ __align__(16) float g_y2[N_NODES * 64];
__device__ __align__(16) float g_h2[N_NODES * 64];
__device__ __align__(16) float g_y3[(size_t)N_NODES * 256];
__device__ __align__(16) float g_s[768];   // [s1|ss1|s2|ss2|s3|ss3]
__device__ __align__(16) float g_ab[768];  // [a1|b1|a2|b2|a3|b3]

__global__ void k_init_stats() {
    int t = threadIdx.x;
    if (t < 768) g_s[t] = 0.0f;
}

// ---- packed f32x2 helpers ----
__device__ __forceinline__ ull ffma2(ull a, ull b, ull c) {
    ull d;
    asm("fma.rn.f32x2 %0, %1, %2, %3;" : "=l"(d) : "l"(a), "l"(b), "l"(c));
    return d;
}
__device__ __forceinline__ ull dup2(float f) {
    ull r;
    asm("mov.b64 %0, {%1, %1};" : "=l"(r) : "f"(f));
    return r;
}
__device__ __forceinline__ float2 unpk(ull v) {
    float2 f;
    asm("mov.b64 {%0, %1}, %2;" : "=f"(f.x), "=f"(f.y) : "l"(v));
    return f;
}

// 4n x 8d packed inner product over one 64-wide K chunk.
// hs: [64 n][68 pad]  (272B rows: float4-aligned; h broadcasts 2-way conflicted, absorbed)
// ws: [64 c][64 d]    (ulonglong2 = 4 consecutive d as 2 packed pairs)
__device__ __forceinline__ void mm_inner2(const float (*hs)[68], const float (*ws)[64],
                                          int ng4, int dg8, ull acc[4][4]) {
#pragma unroll 8
    for (int c = 0; c < 64; ++c) {
        ulonglong2 w0 = *(const ulonglong2*)&ws[c][dg8];
        ulonglong2 w1 = *(const ulonglong2*)&ws[c][dg8 + 4];
        ull h0 = dup2(hs[ng4 + 0][c]);
        ull h1 = dup2(hs[ng4 + 1][c]);
        ull h2 = dup2(hs[ng4 + 2][c]);
        ull h3 = dup2(hs[ng4 + 3][c]);
        acc[0][0] = ffma2(h0, w0.x, acc[0][0]); acc[0][1] = ffma2(h0, w0.y, acc[0][1]);
        acc[0][2] = ffma2(h0, w1.x, acc[0][2]); acc[0][3] = ffma2(h0, w1.y, acc[0][3]);
        acc[1][0] = ffma2(h1, w0.x, acc[1][0]); acc[1][1] = ffma2(h1, w0.y, acc[1][1]);
        acc[1][2] = ffma2(h1, w1.x, acc[1][2]); acc[1][3] = ffma2(h1, w1.y, acc[1][3]);
        acc[2][0] = ffma2(h2, w0.x, acc[2][0]); acc[2][1] = ffma2(h2, w0.y, acc[2][1]);
        acc[2][2] = ffma2(h2, w1.x, acc[2][2]); acc[2][3] = ffma2(h2, w1.y, acc[2][3]);
        acc[3][0] = ffma2(h3, w0.x, acc[3][0]); acc[3][1] = ffma2(h3, w0.y, acc[3][1]);
        acc[3][2] = ffma2(h3, w1.x, acc[3][2]); acc[3][3] = ffma2(h3, w1.y, acc[3][3]);
    }
}

__device__ __forceinline__ void acc_zero(ull acc[4][4]) {
#pragma unroll
    for (int i = 0; i < 4; ++i)
#pragma unroll
        for (int j = 0; j < 4; ++j) acc[i][j] = 0ull;
}

// Store 4n x 8d tile + accumulate per-column sum/sumsq into smem.
__device__ __forceinline__ void epilogue(ull acc[4][4], float* ybase, size_t ystride,
                                         int n0, int ng4, int dg8,
                                         float* csum, float* csq) {
#pragma unroll
    for (int i = 0; i < 4; ++i) {
        float2 p0 = unpk(acc[i][0]), p1 = unpk(acc[i][1]);
        float2 p2 = unpk(acc[i][2]), p3 = unpk(acc[i][3]);
        float* row = ybase + (size_t)(n0 + ng4 + i) * ystride + dg8;
        *(float4*)(row)     = make_float4(p0.x, p0.y, p1.x, p1.y);
        *(float4*)(row + 4) = make_float4(p2.x, p2.y, p3.x, p3.y);
    }
#pragma unroll
    for (int jp = 0; jp < 4; ++jp) {
        float s0 = 0.f, s1 = 0.f, q0 = 0.f, q1 = 0.f;
#pragma unroll
        for (int i = 0; i < 4; ++i) {
            float2 p = unpk(acc[i][jp]);
            s0 += p.x; q0 += p.x * p.x;
            s1 += p.y; q1 += p.y * p.y;
        }
        atomicAdd(&csum[dg8 + 2 * jp],     s0);
        atomicAdd(&csq [dg8 + 2 * jp],     q0);
        atomicAdd(&csum[dg8 + 2 * jp + 1], s1);
        atomicAdd(&csq [dg8 + 2 * jp + 1], q1);
    }
}

// ---- GEMM1: y1 = x @ W1   ([N,256] @ [256,64]) + fused column sum/sumsq ----
__global__ __launch_bounds__(128, 4) void k_gemm1(const float* __restrict__ x,
                                                  const float* __restrict__ W1) {
    __shared__ __align__(16) float hs[64][68];
    __shared__ __align__(16) float ws[64][64];
    __shared__ __align__(16) float csum[64], csq[64];

    int tid = threadIdx.x;
    int n0  = blockIdx.x * 64;
    int dg8 = (tid & 7) * 8;
    int ng4 = (tid >> 3) * 4;
    int c4  = tid & 15;
    int r0  = tid >> 4;       // 0..7

    if (tid < 64) { csum[tid] = 0.0f; csq[tid] = 0.0f; }

    ull acc[4][4];
    acc_zero(acc);

    for (int kc = 0; kc < 4; ++kc) {
#pragma unroll
        for (int it = 0; it < 8; ++it) {
            int r = r0 + it * 8;
            *(float4*)&hs[r][c4 * 4] =
                *(const float4*)&x[(size_t)(n0 + r) * 256 + kc * 64 + c4 * 4];
            *(float4*)&ws[r][c4 * 4] =
                *(const float4*)&W1[(size_t)(kc * 64 + r) * 64 + c4 * 4];
        }
        __syncthreads();
        mm_inner2(hs, ws, ng4, dg8, acc);
        __syncthreads();
    }
    epilogue(acc, g_y1, 64, n0, ng4, dg8, csum, csq);
    __syncthreads();
    if (tid < 64) {
        atomicAdd(&g_s[0  + tid], csum[tid]);
        atomicAdd(&g_s[64 + tid], csq[tid]);
    }
}

// ---- prep BN affine: a = gamma*rsqrt(var+eps), b = beta - mean*a ----
__global__ void k_prep(const float* __restrict__ gamma, const float* __restrict__ beta,
                       int sIdx, int abIdx, int C) {
    int t = threadIdx.x;
    if (t < C) {
        float invN = 1.0f / (float)N_NODES;
        float mean = g_s[sIdx + t] * invN;
        float var  = g_s[sIdx + C + t] * invN - mean * mean;
        float a    = gamma[t] * rsqrtf(var + EPS_BN);
        g_ab[abIdx + t]     = a;
        g_ab[abIdx + C + t] = beta[t] - mean * a;
    }
}

// ---- BN apply + ReLU for 64-wide intermediates ----
__global__ void k_bnapply(int which) {
    const float* y = which ? g_y2 : g_y1;
    float*       h = which ? g_h2 : g_h1;
    int ab = which ? 128 : 0;
    size_t base = ((size_t)blockIdx.x * blockDim.x + threadIdx.x) * 4;
    int d = (int)(base & 63);
    float4 yv = *(const float4*)&y[base];
    float4 a  = *(const float4*)&g_ab[ab + d];
    float4 b  = *(const float4*)&g_ab[ab + 64 + d];
    float4 o;
    o.x = fmaxf(fmaf(yv.x, a.x, b.x), 0.0f);
    o.y = fmaxf(fmaf(yv.y, a.y, b.y), 0.0f);
    o.z = fmaxf(fmaf(yv.z, a.z, b.z), 0.0f);
    o.w = fmaxf(fmaf(yv.w, a.w, b.w), 0.0f);
    *(float4*)&h[base] = o;
}

// ---- GEMM2: y2[n,d] = sum_k sum_c h1[neigh[n,k],c] * W2[k,c,d] + fused stats ----
__global__ __launch_bounds__(128, 4) void k_gemm2(const int* __restrict__ neigh,
                                                  const float* __restrict__ W2) {
    __shared__ __align__(16) float hs[64][68];
    __shared__ __align__(16) float ws[64][64];
    __shared__ __align__(16) int   ns[27 * 64];
    __shared__ __align__(16) float csum[64], csq[64];

    int tid = threadIdx.x;
    int n0  = blockIdx.x * 64;
    int dg8 = (tid & 7) * 8;
    int ng4 = (tid >> 3) * 4;
    int c4  = tid & 15;
    int r0  = tid >> 4;

    if (tid < 64) { csum[tid] = 0.0f; csq[tid] = 0.0f; }

    // neigh tile, transposed to [k][n] for broadcast-friendly reads
    for (int i = tid; i < 27 * 64; i += 128) {
        int n = i / 27;
        int k = i - n * 27;
        ns[k * 64 + n] = neigh[(size_t)n0 * 27 + i];
    }

    ull acc[4][4];
    acc_zero(acc);
    __syncthreads();

    for (int k = 0; k < 27; ++k) {
#pragma unroll
        for (int it = 0; it < 8; ++it) {
            int r   = r0 + it * 8;
            int row = ns[k * 64 + r];
            *(float4*)&hs[r][c4 * 4] =
                *(const float4*)&g_h1[(size_t)row * 64 + c4 * 4];  // L2-resident gather
            *(float4*)&ws[r][c4 * 4] =
                *(const float4*)&W2[(size_t)k * 4096 + r * 64 + c4 * 4];
        }
        __syncthreads();
        mm_inner2(hs, ws, ng4, dg8, acc);
        __syncthreads();
    }
    epilogue(acc, g_y2, 64, n0, ng4, dg8, csum, csq);
    __syncthreads();
    if (tid < 64) {
        atomicAdd(&g_s[128 + tid], csum[tid]);
        atomicAdd(&g_s[192 + tid], csq[tid]);
    }
}

// ---- GEMM3: y3 = h2 @ W3   ([N,64] @ [64,256]) + fused stats ----
__global__ __launch_bounds__(128, 4) void k_gemm3(const float* __restrict__ W3) {
    __shared__ __align__(16) float hs[64][68];
    __shared__ __align__(16) float ws[64][64];
    __shared__ __align__(16) float csum[64], csq[64];

    int tid = threadIdx.x;
    int n0  = blockIdx.x * 64;
    int db  = blockIdx.y * 64;     // output-column chunk
    int dg8 = (tid & 7) * 8;
    int ng4 = (tid >> 3) * 4;
    int c4  = tid & 15;
    int r0  = tid >> 4;

    if (tid < 64) { csum[tid] = 0.0f; csq[tid] = 0.0f; }

    ull acc[4][4];
    acc_zero(acc);

#pragma unroll
    for (int it = 0; it < 8; ++it) {
        int r = r0 + it * 8;
        *(float4*)&hs[r][c4 * 4] =
            *(const float4*)&g_h2[(size_t)(n0 + r) * 64 + c4 * 4];
        *(float4*)&ws[r][c4 * 4] =
            *(const float4*)&W3[(size_t)r * 256 + db + c4 * 4];
    }
    __syncthreads();
    mm_inner2(hs, ws, ng4, dg8, acc);
    __syncthreads();

    // epilogue with 256-wide rows, offset db
#pragma unroll
    for (int i = 0; i < 4; ++i) {
        float2 p0 = unpk(acc[i][0]), p1 = unpk(acc[i][1]);
        float2 p2 = unpk(acc[i][2]), p3 = unpk(acc[i][3]);
        float* row = g_y3 + (size_t)(n0 + ng4 + i) * 256 + db + dg8;
        *(float4*)(row)     = make_float4(p0.x, p0.y, p1.x, p1.y);
        *(float4*)(row + 4) = make_float4(p2.x, p2.y, p3.x, p3.y);
    }
#pragma unroll
    for (int jp = 0; jp < 4; ++jp) {
        float s0 = 0.f, s1 = 0.f, q0 = 0.f, q1 = 0.f;
#pragma unroll
        for (int i = 0; i < 4; ++i) {
            float2 p = unpk(acc[i][jp]);
            s0 += p.x; q0 += p.x * p.x;
            s1 += p.y; q1 += p.y * p.y;
        }
        atomicAdd(&csum[dg8 + 2 * jp],     s0);
        atomicAdd(&csq [dg8 + 2 * jp],     q0);
        atomicAdd(&csum[dg8 + 2 * jp + 1], s1);
        atomicAdd(&csq [dg8 + 2 * jp + 1], q1);
    }
    __syncthreads();
    if (tid < 64) {
        atomicAdd(&g_s[256 + db + tid], csum[tid]);
        atomicAdd(&g_s[512 + db + tid], csq[tid]);
    }
}

// ---- final: out = relu(BN3(y3) + x) ----
__global__ void k_final(const float* __restrict__ x, float* __restrict__ out) {
    size_t base = ((size_t)blockIdx.x * 256 + threadIdx.x) * 4;
    int d = (int)(base & 255);
    float4 yv = *(const float4*)&g_y3[base];
    float4 a  = *(const float4*)&g_ab[256 + d];
    float4 b  = *(const float4*)&g_ab[512 + d];
    float4 xv = *(const float4*)&x[base];
    float4 o;
    o.x = fmaxf(fmaf(yv.x, a.x, b.x) + xv.x, 0.0f);
    o.y = fmaxf(fmaf(yv.y, a.y, b.y) + xv.y, 0.0f);
    o.z = fmaxf(fmaf(yv.z, a.z, b.z) + xv.z, 0.0f);
    o.w = fmaxf(fmaf(yv.w, a.w, b.w) + xv.w, 0.0f);
    *(float4*)&out[base] = o;
}

extern "C" void kernel_launch(void* const* d_in, const int* in_sizes, int n_in,
                              void* d_out, int out_size) {
    const float* x     = (const float*)d_in[0];
    const int*   neigh = (const int*)  d_in[1];
    // d_in[2] = depth (unused)
    const float* W1 = (const float*)d_in[3];
    const float* g1 = (const float*)d_in[4];
    const float* b1 = (const float*)d_in[5];
    const float* W2 = (const float*)d_in[6];
    const float* g2 = (const float*)d_in[7];
    const float* b2 = (const float*)d_in[8];
    const float* W3 = (const float*)d_in[9];
    const float* g3 = (const float*)d_in[10];
    const float* b3 = (const float*)d_in[11];
    float* out = (float*)d_out;

    k_init_stats<<<1, 768>>>();

    k_gemm1<<<NTILES, 128>>>(x, W1);
    k_prep<<<1, 64>>>(g1, b1, /*sIdx=*/0, /*abIdx=*/0, 64);
    k_bnapply<<<12500, 256>>>(0);

    k_gemm2<<<NTILES, 128>>>(neigh, W2);
    k_prep<<<1, 64>>>(g2, b2, /*sIdx=*/128, /*abIdx=*/128, 64);
    k_bnapply<<<12500, 256>>>(1);

    k_gemm3<<<dim3(NTILES, 4), 128>>>(W3);
    k_prep<<<1, 256>>>(g3, b3, /*sIdx=*/256, /*abIdx=*/256, 256);
    k_final<<<50000, 256>>>(x, out);
}